// round 13
// baseline (speedup 1.0000x reference)
#include <cuda_runtime.h>

#define NHX 64
#define NHY 64
#define NU  512
#define NV  512
#define LCH 16
#define NPLANES 6

#define CAPN 1000000
#define TILE_SHIFT 3                 // 8x8 uv cells per tile
#define TPD 64                       // tiles per dim (512 >> 3)
#define NB (8 * TPD * TPD)           // 32768 buckets
#define CAP 48                       // slots per bucket (mean ~30.5 at N=1M)

__device__ int   g_cnt[NB + 1];      // counts + overflow cursor (memset each launch)
__device__ uint4 g_rec[NB * CAP];    // packed record, 16 B/point (25 MB)
__device__ int   g_ovf_pt[CAPN];     // overflow point ids

#define FR_SCALE 65535.0f
#define FR_INV   (1.0f / 65535.0f)

// ---------------- bucketing / packing ----------------

__device__ __forceinline__ int bucket_of(int mi, float uu, float vv) {
    int uc = (int)(uu * (float)NU); if (uc > NU - 1) uc = NU - 1;
    int vc = (int)(vv * (float)NV); if (vc > NV - 1) vc = NV - 1;
    return (mi << 12) | ((uc >> TILE_SHIFT) << 6) | (vc >> TILE_SHIFT);
}

__device__ __forceinline__ void axis_split(float ind, int I, int& i1, unsigned& f16) {
    if (ind == (float)I) ind = (float)(I - 1);
    i1 = (int)ind;
    float fr = ind - (float)i1;
    f16 = (unsigned)(fr * FR_SCALE + 0.5f);
}

__global__ void __launch_bounds__(256)
scatter_kernel(const int* __restrict__ m,
               const float* __restrict__ h,
               const float* __restrict__ u,
               const float* __restrict__ v, int N) {
    int pt = blockIdx.x * blockDim.x + threadIdx.x;
    if (pt >= N) return;
    int   mi = m[pt];
    float uu = u[pt], vv = v[pt];
    float2 hh = *reinterpret_cast<const float2*>(h + 2 * pt);

    int b = bucket_of(mi, uu, vv);
    int pos = atomicAdd(&g_cnt[b], 1);
    if (pos < CAP) {
        float ind_hx = (hh.x + 1.0f) / 2.0f * (float)NHX;
        float ind_hy = (hh.y + 1.0f) / 2.0f * (float)NHY;
        float ind_u  = uu * (float)NU;
        float ind_v  = vv * (float)NV;
        int x1, y1, u1, v1; unsigned fx, fy, fu, fv;
        axis_split(ind_hx, NHX, x1, fx);
        axis_split(ind_hy, NHY, y1, fy);
        axis_split(ind_u,  NU,  u1, fu);
        axis_split(ind_v,  NV,  v1, fv);

        uint4 rec;
        rec.x = (fx << 16) | fy;
        rec.y = (fu << 16) | fv;
        rec.z = (unsigned)x1 | ((unsigned)y1 << 6) | ((unsigned)u1 << 12) | ((unsigned)v1 << 21);
        rec.w = (unsigned)pt;
        __stcs(&g_rec[b * CAP + pos], rec);
    } else {
        int o = atomicAdd(&g_cnt[NB], 1);
        if (o < CAPN) g_ovf_pt[o] = pt;
    }
}

// ---------------- interpolation core ----------------

__device__ __forceinline__ float4 bilerp4(const float* __restrict__ F,
                                          int mi, int I, int J,
                                          int i1, int i2, float ir,
                                          int j1, int j2, float jr, int q) {
    int rowA = (mi * I + i1) * J;
    int rowB = (mi * I + i2) * J;
    const float4* p11 = reinterpret_cast<const float4*>(F) + (rowA + j1) * 4 + q;
    const float4* p21 = reinterpret_cast<const float4*>(F) + (rowB + j1) * 4 + q;
    const float4* p12 = reinterpret_cast<const float4*>(F) + (rowA + j2) * 4 + q;
    const float4* p22 = reinterpret_cast<const float4*>(F) + (rowB + j2) * 4 + q;
    float4 a = __ldg(p11);
    float4 b = __ldg(p21);
    float4 c = __ldg(p12);
    float4 d = __ldg(p22);
    float omi = 1.0f - ir, omj = 1.0f - jr;
    float4 out;
    out.x = (a.x * omi + b.x * ir) * omj + (c.x * omi + d.x * ir) * jr;
    out.y = (a.y * omi + b.y * ir) * omj + (c.y * omi + d.y * ir) * jr;
    out.z = (a.z * omi + b.z * ir) * omj + (c.z * omi + d.z * ir) * jr;
    out.w = (a.w * omi + b.w * ir) * omj + (c.w * omi + d.w * ir) * jr;
    return out;
}

// exact axis (overflow + fallback paths)
__device__ __forceinline__ void axis(float ind, int I, int& i1, int& i2, float& fr) {
    if (ind == (float)I) ind = (float)(I - 1);
    i1 = (int)ind;
    fr = ind - (float)i1;
    i2 = i1 + 1;
    if (i2 == I) i2 = 0;
}

__device__ __forceinline__ void interp_core(int mi, int pt, int q,
                                            int x1, int x2, float xr,
                                            int y1, int y2, float yr,
                                            int u1, int u2, float ur,
                                            int v1, int v2, float vr,
                                            const float* __restrict__ Fxy,
                                            const float* __restrict__ Fxu,
                                            const float* __restrict__ Fxv,
                                            const float* __restrict__ Fyu,
                                            const float* __restrict__ Fyv,
                                            const float* __restrict__ Fuv,
                                            float4* __restrict__ out) {
    float4* o = out + (size_t)pt * (NPLANES * (LCH / 4));
    __stcs(&o[0 * 4 + q], bilerp4(Fxy, mi, NHX, NHY, x1, x2, xr, y1, y2, yr, q));
    __stcs(&o[1 * 4 + q], bilerp4(Fxu, mi, NHX, NU,  x1, x2, xr, u1, u2, ur, q));
    __stcs(&o[2 * 4 + q], bilerp4(Fxv, mi, NHX, NV,  x1, x2, xr, v1, v2, vr, q));
    __stcs(&o[3 * 4 + q], bilerp4(Fyu, mi, NHY, NU,  y1, y2, yr, u1, u2, ur, q));
    __stcs(&o[4 * 4 + q], bilerp4(Fyv, mi, NHY, NV,  y1, y2, yr, v1, v2, vr, q));
    __stcs(&o[5 * 4 + q], bilerp4(Fuv, mi, NU,  NV,  u1, u2, ur, v1, v2, vr, q));
}

__device__ __forceinline__ void interp_point(float hx, float hy, float uu, float vv,
                                             int mi, int pt, int q,
                                             const float* __restrict__ Fxy,
                                             const float* __restrict__ Fxu,
                                             const float* __restrict__ Fxv,
                                             const float* __restrict__ Fyu,
                                             const float* __restrict__ Fyv,
                                             const float* __restrict__ Fuv,
                                             float4* __restrict__ out) {
    float ind_hx = (hx + 1.0f) / 2.0f * (float)NHX;
    float ind_hy = (hy + 1.0f) / 2.0f * (float)NHY;
    float ind_u  = uu * (float)NU;
    float ind_v  = vv * (float)NV;
    int x1, x2, y1, y2, u1, u2, v1, v2;
    float xr, yr, ur, vr;
    axis(ind_hx, NHX, x1, x2, xr);
    axis(ind_hy, NHY, y1, y2, yr);
    axis(ind_u,  NU,  u1, u2, ur);
    axis(ind_v,  NV,  v1, v2, vr);
    interp_core(mi, pt, q, x1, x2, xr, y1, y2, yr, u1, u2, ur, v1, v2, vr,
                Fxy, Fxu, Fxv, Fyu, Fyv, Fuv, out);
}

// ---------------- main kernels ----------------

#define TPB_MAIN 192                 // 48 slots x 4 lanes: 1 block per bucket

__global__ void __launch_bounds__(TPB_MAIN)
triplane_bucket_kernel(const float* __restrict__ Fxy,
                       const float* __restrict__ Fxu,
                       const float* __restrict__ Fxv,
                       const float* __restrict__ Fyu,
                       const float* __restrict__ Fyv,
                       const float* __restrict__ Fuv,
                       float4*      __restrict__ out) {
    int bucket = blockIdx.x;
    int t    = threadIdx.x;
    int slot = t >> 2;
    int q    = t & 3;

    int cnt = g_cnt[bucket];
    if (cnt > CAP) cnt = CAP;
    if (slot >= cnt) return;

    uint4 rec = __ldcs(&g_rec[bucket * CAP + slot]);
    int pt = (int)rec.w;
    int mi = bucket >> 12;

    float xr = (float)(rec.x >> 16)     * FR_INV;
    float yr = (float)(rec.x & 0xFFFF)  * FR_INV;
    float ur = (float)(rec.y >> 16)     * FR_INV;
    float vr = (float)(rec.y & 0xFFFF)  * FR_INV;

    int x1 =  rec.z        & 63;
    int y1 = (rec.z >> 6)  & 63;
    int u1 = (rec.z >> 12) & 511;
    int v1 = (rec.z >> 21) & 511;

    int x2 = (x1 + 1) & (NHX - 1);
    int y2 = (y1 + 1) & (NHY - 1);
    int u2 = (u1 + 1) & (NU - 1);
    int v2 = (v1 + 1) & (NV - 1);

    interp_core(mi, pt, q, x1, x2, xr, y1, y2, yr, u1, u2, ur, v1, v2, vr,
                Fxy, Fxu, Fxv, Fyu, Fyv, Fuv, out);
}

// Overflow (normally zero points): small separate launch, raw inputs, exact path.
__global__ void __launch_bounds__(256)
triplane_overflow_kernel(const int*   __restrict__ m,
                         const float* __restrict__ h,
                         const float* __restrict__ u,
                         const float* __restrict__ v,
                         const float* __restrict__ Fxy,
                         const float* __restrict__ Fxu,
                         const float* __restrict__ Fxv,
                         const float* __restrict__ Fyu,
                         const float* __restrict__ Fyv,
                         const float* __restrict__ Fuv,
                         float4*      __restrict__ out) {
    int n = g_cnt[NB];
    if (n > CAPN) n = CAPN;
    int total = n * 4;
    for (int i = blockIdx.x * blockDim.x + threadIdx.x; i < total;
         i += gridDim.x * blockDim.x) {
        int k  = i >> 2;
        int q  = i & 3;
        int pt = g_ovf_pt[k];
        int mi = m[pt];
        interp_point(h[2 * pt], h[2 * pt + 1], u[pt], v[pt], mi, pt, q,
                     Fxy, Fxu, Fxv, Fyu, Fyv, Fuv, out);
    }
}

// Fallback if N exceeds static scratch capacity: direct, unsorted, exact.
__global__ void __launch_bounds__(256)
triplane_direct_kernel(const int*   __restrict__ m,
                       const float* __restrict__ h,
                       const float* __restrict__ u,
                       const float* __restrict__ v,
                       const float* __restrict__ Fxy,
                       const float* __restrict__ Fxu,
                       const float* __restrict__ Fxv,
                       const float* __restrict__ Fyu,
                       const float* __restrict__ Fyv,
                       const float* __restrict__ Fuv,
                       float4*      __restrict__ out,
                       int N) {
    int gid = blockIdx.x * blockDim.x + threadIdx.x;
    int pt  = gid >> 2;
    int q   = gid & 3;
    if (pt >= N) return;
    int mi = m[pt];
    interp_point(h[2 * pt], h[2 * pt + 1], u[pt], v[pt], mi, pt, q,
                 Fxy, Fxu, Fxv, Fyu, Fyv, Fuv, out);
}

extern "C" void kernel_launch(void* const* d_in, const int* in_sizes, int n_in,
                              void* d_out, int out_size) {
    // order: r, m, h, u, v, Fxy, Fxu, Fxv, Fyu, Fyv, Fuv   (r unused)
    const int*   m   = (const int*)  d_in[1];
    const float* h   = (const float*)d_in[2];
    const float* u   = (const float*)d_in[3];
    const float* v   = (const float*)d_in[4];
    const float* Fxy = (const float*)d_in[5];
    const float* Fxu = (const float*)d_in[6];
    const float* Fxv = (const float*)d_in[7];
    const float* Fyu = (const float*)d_in[8];
    const float* Fyv = (const float*)d_in[9];
    const float* Fuv = (const float*)d_in[10];

    int N = in_sizes[1];
    int tpb = 256;

    if (N <= CAPN) {
        void* cnt_addr = nullptr;
        cudaGetSymbolAddress(&cnt_addr, g_cnt);
        cudaMemsetAsync(cnt_addr, 0, (NB + 1) * sizeof(int));

        scatter_kernel<<<(N + tpb - 1) / tpb, tpb>>>(m, h, u, v, N);
        triplane_bucket_kernel<<<NB, TPB_MAIN>>>(
            Fxy, Fxu, Fxv, Fyu, Fyv, Fuv, (float4*)d_out);
        triplane_overflow_kernel<<<64, tpb>>>(
            m, h, u, v, Fxy, Fxu, Fxv, Fyu, Fyv, Fuv, (float4*)d_out);
    } else {
        long long tt = (long long)N * 4;
        triplane_direct_kernel<<<(int)((tt + tpb - 1) / tpb), tpb>>>(
            m, h, u, v, Fxy, Fxu, Fxv, Fyu, Fyv, Fuv, (float4*)d_out, N);
    }
}

// round 14
// speedup vs baseline: 1.0003x; 1.0003x over previous
#include <cuda_runtime.h>

#define NHX 64
#define NHY 64
#define NU  512
#define NV  512
#define LCH 16
#define NPLANES 6

#define CAPN 1000000
#define TILE_SHIFT 4                 // 16x16 uv cells per tile
#define TPD 32                       // tiles per dim (512 >> 4)
#define NB (8 * TPD * TPD)           // 8192 buckets
#define NSEG 3                       // sub-counters per bucket (one per 64-slot segment)
#define SEG_CAP 64                   // slots per segment
#define CAP (NSEG * SEG_CAP)         // 192 slots per bucket (R9 geometry)

// g_cnt[bucket*NSEG + seg] = per-segment counts; g_cnt[NB*NSEG] = overflow cursor.
__device__ int   g_cnt[NB * NSEG + 1];
__device__ uint4 g_rec[NB * CAP];    // packed record, 16 B/point (25 MB)
__device__ int   g_ovf_pt[CAPN];     // overflow point ids

#define FR_SCALE 65535.0f
#define FR_INV   (1.0f / 65535.0f)

// ---------------- bucketing / packing ----------------

__device__ __forceinline__ int bucket_of(int mi, float uu, float vv) {
    int uc = (int)(uu * (float)NU); if (uc > NU - 1) uc = NU - 1;
    int vc = (int)(vv * (float)NV); if (vc > NV - 1) vc = NV - 1;
    return (mi << 10) | ((uc >> TILE_SHIFT) << 5) | (vc >> TILE_SHIFT);
}

__device__ __forceinline__ void axis_split(float ind, int I, int& i1, unsigned& f16) {
    if (ind == (float)I) ind = (float)(I - 1);
    i1 = (int)ind;
    float fr = ind - (float)i1;
    f16 = (unsigned)(fr * FR_SCALE + 0.5f);
}

__global__ void __launch_bounds__(256)
scatter_kernel(const int* __restrict__ m,
               const float* __restrict__ h,
               const float* __restrict__ u,
               const float* __restrict__ v, int N) {
    int pt = blockIdx.x * blockDim.x + threadIdx.x;
    if (pt >= N) return;
    int   mi = m[pt];
    float uu = u[pt], vv = v[pt];
    float2 hh = *reinterpret_cast<const float2*>(h + 2 * pt);

    int b   = bucket_of(mi, uu, vv);
    int seg = pt % NSEG;
    int pos = atomicAdd(&g_cnt[b * NSEG + seg], 1);
    if (pos < SEG_CAP) {
        float ind_hx = (hh.x + 1.0f) / 2.0f * (float)NHX;
        float ind_hy = (hh.y + 1.0f) / 2.0f * (float)NHY;
        float ind_u  = uu * (float)NU;
        float ind_v  = vv * (float)NV;
        int x1, y1, u1, v1; unsigned fx, fy, fu, fv;
        axis_split(ind_hx, NHX, x1, fx);
        axis_split(ind_hy, NHY, y1, fy);
        axis_split(ind_u,  NU,  u1, fu);
        axis_split(ind_v,  NV,  v1, fv);

        uint4 rec;
        rec.x = (fx << 16) | fy;
        rec.y = (fu << 16) | fv;
        rec.z = (unsigned)x1 | ((unsigned)y1 << 6) | ((unsigned)u1 << 12) | ((unsigned)v1 << 21);
        rec.w = (unsigned)pt;
        __stcs(&g_rec[b * CAP + seg * SEG_CAP + pos], rec);
    } else {
        int o = atomicAdd(&g_cnt[NB * NSEG], 1);
        if (o < CAPN) g_ovf_pt[o] = pt;
    }
}

// ---------------- interpolation core ----------------

__device__ __forceinline__ float4 bilerp4(const float* __restrict__ F,
                                          int mi, int I, int J,
                                          int i1, int i2, float ir,
                                          int j1, int j2, float jr, int q) {
    int rowA = (mi * I + i1) * J;
    int rowB = (mi * I + i2) * J;
    const float4* p11 = reinterpret_cast<const float4*>(F) + (rowA + j1) * 4 + q;
    const float4* p21 = reinterpret_cast<const float4*>(F) + (rowB + j1) * 4 + q;
    const float4* p12 = reinterpret_cast<const float4*>(F) + (rowA + j2) * 4 + q;
    const float4* p22 = reinterpret_cast<const float4*>(F) + (rowB + j2) * 4 + q;
    float4 a = __ldg(p11);
    float4 b = __ldg(p21);
    float4 c = __ldg(p12);
    float4 d = __ldg(p22);
    float omi = 1.0f - ir, omj = 1.0f - jr;
    float4 out;
    out.x = (a.x * omi + b.x * ir) * omj + (c.x * omi + d.x * ir) * jr;
    out.y = (a.y * omi + b.y * ir) * omj + (c.y * omi + d.y * ir) * jr;
    out.z = (a.z * omi + b.z * ir) * omj + (c.z * omi + d.z * ir) * jr;
    out.w = (a.w * omi + b.w * ir) * omj + (c.w * omi + d.w * ir) * jr;
    return out;
}

// exact axis (overflow + fallback paths)
__device__ __forceinline__ void axis(float ind, int I, int& i1, int& i2, float& fr) {
    if (ind == (float)I) ind = (float)(I - 1);
    i1 = (int)ind;
    fr = ind - (float)i1;
    i2 = i1 + 1;
    if (i2 == I) i2 = 0;
}

__device__ __forceinline__ void interp_core(int mi, int pt, int q,
                                            int x1, int x2, float xr,
                                            int y1, int y2, float yr,
                                            int u1, int u2, float ur,
                                            int v1, int v2, float vr,
                                            const float* __restrict__ Fxy,
                                            const float* __restrict__ Fxu,
                                            const float* __restrict__ Fxv,
                                            const float* __restrict__ Fyu,
                                            const float* __restrict__ Fyv,
                                            const float* __restrict__ Fuv,
                                            float4* __restrict__ out) {
    float4* o = out + (size_t)pt * (NPLANES * (LCH / 4));
    __stcs(&o[0 * 4 + q], bilerp4(Fxy, mi, NHX, NHY, x1, x2, xr, y1, y2, yr, q));
    __stcs(&o[1 * 4 + q], bilerp4(Fxu, mi, NHX, NU,  x1, x2, xr, u1, u2, ur, q));
    __stcs(&o[2 * 4 + q], bilerp4(Fxv, mi, NHX, NV,  x1, x2, xr, v1, v2, vr, q));
    __stcs(&o[3 * 4 + q], bilerp4(Fyu, mi, NHY, NU,  y1, y2, yr, u1, u2, ur, q));
    __stcs(&o[4 * 4 + q], bilerp4(Fyv, mi, NHY, NV,  y1, y2, yr, v1, v2, vr, q));
    __stcs(&o[5 * 4 + q], bilerp4(Fuv, mi, NU,  NV,  u1, u2, ur, v1, v2, vr, q));
}

__device__ __forceinline__ void interp_point(float hx, float hy, float uu, float vv,
                                             int mi, int pt, int q,
                                             const float* __restrict__ Fxy,
                                             const float* __restrict__ Fxu,
                                             const float* __restrict__ Fxv,
                                             const float* __restrict__ Fyu,
                                             const float* __restrict__ Fyv,
                                             const float* __restrict__ Fuv,
                                             float4* __restrict__ out) {
    float ind_hx = (hx + 1.0f) / 2.0f * (float)NHX;
    float ind_hy = (hy + 1.0f) / 2.0f * (float)NHY;
    float ind_u  = uu * (float)NU;
    float ind_v  = vv * (float)NV;
    int x1, x2, y1, y2, u1, u2, v1, v2;
    float xr, yr, ur, vr;
    axis(ind_hx, NHX, x1, x2, xr);
    axis(ind_hy, NHY, y1, y2, yr);
    axis(ind_u,  NU,  u1, u2, ur);
    axis(ind_v,  NV,  v1, v2, vr);
    interp_core(mi, pt, q, x1, x2, xr, y1, y2, yr, u1, u2, ur, v1, v2, vr,
                Fxy, Fxu, Fxv, Fyu, Fyv, Fuv, out);
}

// ---------------- main kernels (R9 geometry: 3 blocks of 64 slots per bucket) ----------------

#define TPB_MAIN 256
#define SLOTS_PER_BLOCK (TPB_MAIN / 4)                 // 64 == SEG_CAP

__global__ void __launch_bounds__(TPB_MAIN)
triplane_bucket_kernel(const float* __restrict__ Fxy,
                       const float* __restrict__ Fxu,
                       const float* __restrict__ Fxv,
                       const float* __restrict__ Fyu,
                       const float* __restrict__ Fyv,
                       const float* __restrict__ Fuv,
                       float4*      __restrict__ out) {
    int bucket = blockIdx.x / NSEG;
    int seg    = blockIdx.x % NSEG;
    int t    = threadIdx.x;
    int slot = t >> 2;
    int q    = t & 3;

    int cnt = g_cnt[bucket * NSEG + seg];
    if (cnt > SEG_CAP) cnt = SEG_CAP;
    if (slot >= cnt) return;

    uint4 rec = __ldcs(&g_rec[bucket * CAP + seg * SEG_CAP + slot]);
    int pt = (int)rec.w;
    int mi = bucket >> 10;

    float xr = (float)(rec.x >> 16)     * FR_INV;
    float yr = (float)(rec.x & 0xFFFF)  * FR_INV;
    float ur = (float)(rec.y >> 16)     * FR_INV;
    float vr = (float)(rec.y & 0xFFFF)  * FR_INV;

    int x1 =  rec.z        & 63;
    int y1 = (rec.z >> 6)  & 63;
    int u1 = (rec.z >> 12) & 511;
    int v1 = (rec.z >> 21) & 511;

    int x2 = (x1 + 1) & (NHX - 1);
    int y2 = (y1 + 1) & (NHY - 1);
    int u2 = (u1 + 1) & (NU - 1);
    int v2 = (v1 + 1) & (NV - 1);

    interp_core(mi, pt, q, x1, x2, xr, y1, y2, yr, u1, u2, ur, v1, v2, vr,
                Fxy, Fxu, Fxv, Fyu, Fyv, Fuv, out);
}

// Overflow (normally a handful of points): separate small launch, exact path.
__global__ void __launch_bounds__(256)
triplane_overflow_kernel(const int*   __restrict__ m,
                         const float* __restrict__ h,
                         const float* __restrict__ u,
                         const float* __restrict__ v,
                         const float* __restrict__ Fxy,
                         const float* __restrict__ Fxu,
                         const float* __restrict__ Fxv,
                         const float* __restrict__ Fyu,
                         const float* __restrict__ Fyv,
                         const float* __restrict__ Fuv,
                         float4*      __restrict__ out) {
    int n = g_cnt[NB * NSEG];
    if (n > CAPN) n = CAPN;
    int total = n * 4;
    for (int i = blockIdx.x * blockDim.x + threadIdx.x; i < total;
         i += gridDim.x * blockDim.x) {
        int k  = i >> 2;
        int q  = i & 3;
        int pt = g_ovf_pt[k];
        int mi = m[pt];
        interp_point(h[2 * pt], h[2 * pt + 1], u[pt], v[pt], mi, pt, q,
                     Fxy, Fxu, Fxv, Fyu, Fyv, Fuv, out);
    }
}

// Fallback if N exceeds static scratch capacity: direct, unsorted, exact.
__global__ void __launch_bounds__(256)
triplane_direct_kernel(const int*   __restrict__ m,
                       const float* __restrict__ h,
                       const float* __restrict__ u,
                       const float* __restrict__ v,
                       const float* __restrict__ Fxy,
                       const float* __restrict__ Fxu,
                       const float* __restrict__ Fxv,
                       const float* __restrict__ Fyu,
                       const float* __restrict__ Fyv,
                       const float* __restrict__ Fuv,
                       float4*      __restrict__ out,
                       int N) {
    int gid = blockIdx.x * blockDim.x + threadIdx.x;
    int pt  = gid >> 2;
    int q   = gid & 3;
    if (pt >= N) return;
    int mi = m[pt];
    interp_point(h[2 * pt], h[2 * pt + 1], u[pt], v[pt], mi, pt, q,
                 Fxy, Fxu, Fxv, Fyu, Fyv, Fuv, out);
}

extern "C" void kernel_launch(void* const* d_in, const int* in_sizes, int n_in,
                              void* d_out, int out_size) {
    // order: r, m, h, u, v, Fxy, Fxu, Fxv, Fyu, Fyv, Fuv   (r unused)
    const int*   m   = (const int*)  d_in[1];
    const float* h   = (const float*)d_in[2];
    const float* u   = (const float*)d_in[3];
    const float* v   = (const float*)d_in[4];
    const float* Fxy = (const float*)d_in[5];
    const float* Fxu = (const float*)d_in[6];
    const float* Fxv = (const float*)d_in[7];
    const float* Fyu = (const float*)d_in[8];
    const float* Fyv = (const float*)d_in[9];
    const float* Fuv = (const float*)d_in[10];

    int N = in_sizes[1];
    int tpb = 256;

    if (N <= CAPN) {
        void* cnt_addr = nullptr;
        cudaGetSymbolAddress(&cnt_addr, g_cnt);
        cudaMemsetAsync(cnt_addr, 0, (NB * NSEG + 1) * sizeof(int));

        scatter_kernel<<<(N + tpb - 1) / tpb, tpb>>>(m, h, u, v, N);
        triplane_bucket_kernel<<<NB * NSEG, TPB_MAIN>>>(
            Fxy, Fxu, Fxv, Fyu, Fyv, Fuv, (float4*)d_out);
        triplane_overflow_kernel<<<64, tpb>>>(
            m, h, u, v, Fxy, Fxu, Fxv, Fyu, Fyv, Fuv, (float4*)d_out);
    } else {
        long long tt = (long long)N * 4;
        triplane_direct_kernel<<<(int)((tt + tpb - 1) / tpb), tpb>>>(
            m, h, u, v, Fxy, Fxu, Fxv, Fyu, Fyv, Fuv, (float4*)d_out, N);
    }
}

// round 15
// speedup vs baseline: 1.0445x; 1.0441x over previous
#include <cuda_runtime.h>

#define NHX 64
#define NHY 64
#define NU  512
#define NV  512
#define LCH 16
#define NPLANES 6

#define CAPN 1000000
#define TILE_SHIFT 4                 // 16x16 uv cells per tile
#define TPD 32                       // tiles per dim (512 >> 4)
#define NB (8 * TPD * TPD)           // 8192 buckets
#define NSEG 3                       // sub-counters per bucket (contention relief)
#define SEG_CAP 64                   // slots per segment
#define CAP (NSEG * SEG_CAP)         // 192 slots per bucket

// g_cnt[bucket*NSEG + seg]; g_cnt[NB*NSEG] = overflow cursor.
__device__ int   g_cnt[NB * NSEG + 1];
__device__ uint4 g_rec[NB * CAP];    // packed record, 16 B/point (25 MB)
__device__ int   g_ovf_pt[CAPN];     // overflow point ids

#define FR_SCALE 65535.0f
#define FR_INV   (1.0f / 65535.0f)

// ---------------- bucketing / packing ----------------

__device__ __forceinline__ int bucket_of(int mi, float uu, float vv) {
    int uc = (int)(uu * (float)NU); if (uc > NU - 1) uc = NU - 1;
    int vc = (int)(vv * (float)NV); if (vc > NV - 1) vc = NV - 1;
    return (mi << 10) | ((uc >> TILE_SHIFT) << 5) | (vc >> TILE_SHIFT);
}

__device__ __forceinline__ void axis_split(float ind, int I, int& i1, unsigned& f16) {
    if (ind == (float)I) ind = (float)(I - 1);
    i1 = (int)ind;
    float fr = ind - (float)i1;
    f16 = (unsigned)(fr * FR_SCALE + 0.5f);
}

__global__ void __launch_bounds__(256)
scatter_kernel(const int* __restrict__ m,
               const float* __restrict__ h,
               const float* __restrict__ u,
               const float* __restrict__ v, int N) {
    int pt = blockIdx.x * blockDim.x + threadIdx.x;
    if (pt >= N) return;
    int   mi = m[pt];
    float uu = u[pt], vv = v[pt];
    float2 hh = *reinterpret_cast<const float2*>(h + 2 * pt);

    int b   = bucket_of(mi, uu, vv);
    int seg = pt % NSEG;
    int pos = atomicAdd(&g_cnt[b * NSEG + seg], 1);
    if (pos < SEG_CAP) {
        float ind_hx = (hh.x + 1.0f) / 2.0f * (float)NHX;
        float ind_hy = (hh.y + 1.0f) / 2.0f * (float)NHY;
        float ind_u  = uu * (float)NU;
        float ind_v  = vv * (float)NV;
        int x1, y1, u1, v1; unsigned fx, fy, fu, fv;
        axis_split(ind_hx, NHX, x1, fx);
        axis_split(ind_hy, NHY, y1, fy);
        axis_split(ind_u,  NU,  u1, fu);
        axis_split(ind_v,  NV,  v1, fv);

        uint4 rec;
        rec.x = (fx << 16) | fy;
        rec.y = (fu << 16) | fv;
        rec.z = (unsigned)x1 | ((unsigned)y1 << 6) | ((unsigned)u1 << 12) | ((unsigned)v1 << 21);
        rec.w = (unsigned)pt;
        __stcs(&g_rec[b * CAP + seg * SEG_CAP + pos], rec);
    } else {
        int o = atomicAdd(&g_cnt[NB * NSEG], 1);
        if (o < CAPN) g_ovf_pt[o] = pt;
    }
}

// ---------------- interpolation core ----------------

__device__ __forceinline__ float4 bilerp4(const float* __restrict__ F,
                                          int mi, int I, int J,
                                          int i1, int i2, float ir,
                                          int j1, int j2, float jr, int q) {
    int rowA = (mi * I + i1) * J;
    int rowB = (mi * I + i2) * J;
    const float4* p11 = reinterpret_cast<const float4*>(F) + (rowA + j1) * 4 + q;
    const float4* p21 = reinterpret_cast<const float4*>(F) + (rowB + j1) * 4 + q;
    const float4* p12 = reinterpret_cast<const float4*>(F) + (rowA + j2) * 4 + q;
    const float4* p22 = reinterpret_cast<const float4*>(F) + (rowB + j2) * 4 + q;
    float4 a = __ldg(p11);
    float4 b = __ldg(p21);
    float4 c = __ldg(p12);
    float4 d = __ldg(p22);
    float omi = 1.0f - ir, omj = 1.0f - jr;
    float4 out;
    out.x = (a.x * omi + b.x * ir) * omj + (c.x * omi + d.x * ir) * jr;
    out.y = (a.y * omi + b.y * ir) * omj + (c.y * omi + d.y * ir) * jr;
    out.z = (a.z * omi + b.z * ir) * omj + (c.z * omi + d.z * ir) * jr;
    out.w = (a.w * omi + b.w * ir) * omj + (c.w * omi + d.w * ir) * jr;
    return out;
}

// exact axis (overflow + fallback paths)
__device__ __forceinline__ void axis(float ind, int I, int& i1, int& i2, float& fr) {
    if (ind == (float)I) ind = (float)(I - 1);
    i1 = (int)ind;
    fr = ind - (float)i1;
    i2 = i1 + 1;
    if (i2 == I) i2 = 0;
}

__device__ __forceinline__ void interp_core(int mi, int pt, int q,
                                            int x1, int x2, float xr,
                                            int y1, int y2, float yr,
                                            int u1, int u2, float ur,
                                            int v1, int v2, float vr,
                                            const float* __restrict__ Fxy,
                                            const float* __restrict__ Fxu,
                                            const float* __restrict__ Fxv,
                                            const float* __restrict__ Fyu,
                                            const float* __restrict__ Fyv,
                                            const float* __restrict__ Fuv,
                                            float4* __restrict__ out) {
    float4* o = out + (size_t)pt * (NPLANES * (LCH / 4));
    __stcs(&o[0 * 4 + q], bilerp4(Fxy, mi, NHX, NHY, x1, x2, xr, y1, y2, yr, q));
    __stcs(&o[1 * 4 + q], bilerp4(Fxu, mi, NHX, NU,  x1, x2, xr, u1, u2, ur, q));
    __stcs(&o[2 * 4 + q], bilerp4(Fxv, mi, NHX, NV,  x1, x2, xr, v1, v2, vr, q));
    __stcs(&o[3 * 4 + q], bilerp4(Fyu, mi, NHY, NU,  y1, y2, yr, u1, u2, ur, q));
    __stcs(&o[4 * 4 + q], bilerp4(Fyv, mi, NHY, NV,  y1, y2, yr, v1, v2, vr, q));
    __stcs(&o[5 * 4 + q], bilerp4(Fuv, mi, NU,  NV,  u1, u2, ur, v1, v2, vr, q));
}

__device__ __forceinline__ void interp_point(float hx, float hy, float uu, float vv,
                                             int mi, int pt, int q,
                                             const float* __restrict__ Fxy,
                                             const float* __restrict__ Fxu,
                                             const float* __restrict__ Fxv,
                                             const float* __restrict__ Fyu,
                                             const float* __restrict__ Fyv,
                                             const float* __restrict__ Fuv,
                                             float4* __restrict__ out) {
    float ind_hx = (hx + 1.0f) / 2.0f * (float)NHX;
    float ind_hy = (hy + 1.0f) / 2.0f * (float)NHY;
    float ind_u  = uu * (float)NU;
    float ind_v  = vv * (float)NV;
    int x1, x2, y1, y2, u1, u2, v1, v2;
    float xr, yr, ur, vr;
    axis(ind_hx, NHX, x1, x2, xr);
    axis(ind_hy, NHY, y1, y2, yr);
    axis(ind_u,  NU,  u1, u2, ur);
    axis(ind_v,  NV,  v1, v2, vr);
    interp_core(mi, pt, q, x1, x2, xr, y1, y2, yr, u1, u2, ur, v1, v2, vr,
                Fxy, Fxu, Fxv, Fyu, Fyv, Fuv, out);
}

// ---------------- main kernels (dense index over segmented storage) ----------------

#define TPB_MAIN 256
#define SLOTS_PER_BLOCK (TPB_MAIN / 4)                 // 64
#define BLOCKS_PER_BUCKET NSEG                         // 3 (covers CAP=192 dense)

__global__ void __launch_bounds__(TPB_MAIN)
triplane_bucket_kernel(const float* __restrict__ Fxy,
                       const float* __restrict__ Fxu,
                       const float* __restrict__ Fxv,
                       const float* __restrict__ Fyu,
                       const float* __restrict__ Fyv,
                       const float* __restrict__ Fuv,
                       float4*      __restrict__ out) {
    int bucket = blockIdx.x / BLOCKS_PER_BUCKET;
    int sbase  = (blockIdx.x % BLOCKS_PER_BUCKET) * SLOTS_PER_BLOCK;
    int t = threadIdx.x;
    int q = t & 3;

    // read the 3 segment counts (same 128B line, broadcast)
    int c0 = g_cnt[bucket * NSEG + 0]; if (c0 > SEG_CAP) c0 = SEG_CAP;
    int c1 = g_cnt[bucket * NSEG + 1]; if (c1 > SEG_CAP) c1 = SEG_CAP;
    int c2 = g_cnt[bucket * NSEG + 2]; if (c2 > SEG_CAP) c2 = SEG_CAP;
    int total = c0 + c1 + c2;

    int i = sbase + (t >> 2);       // dense index within bucket
    if (i >= total) return;

    // dense index -> (segment, position)
    int seg, pos;
    if (i < c0)            { seg = 0; pos = i; }
    else if (i < c0 + c1)  { seg = 1; pos = i - c0; }
    else                   { seg = 2; pos = i - c0 - c1; }

    uint4 rec = __ldcs(&g_rec[bucket * CAP + seg * SEG_CAP + pos]);
    int pt = (int)rec.w;
    int mi = bucket >> 10;

    float xr = (float)(rec.x >> 16)     * FR_INV;
    float yr = (float)(rec.x & 0xFFFF)  * FR_INV;
    float ur = (float)(rec.y >> 16)     * FR_INV;
    float vr = (float)(rec.y & 0xFFFF)  * FR_INV;

    int x1 =  rec.z        & 63;
    int y1 = (rec.z >> 6)  & 63;
    int u1 = (rec.z >> 12) & 511;
    int v1 = (rec.z >> 21) & 511;

    int x2 = (x1 + 1) & (NHX - 1);
    int y2 = (y1 + 1) & (NHY - 1);
    int u2 = (u1 + 1) & (NU - 1);
    int v2 = (v1 + 1) & (NV - 1);

    interp_core(mi, pt, q, x1, x2, xr, y1, y2, yr, u1, u2, ur, v1, v2, vr,
                Fxy, Fxu, Fxv, Fyu, Fyv, Fuv, out);
}

// Overflow (normally a handful of points): separate small launch, exact path.
__global__ void __launch_bounds__(256)
triplane_overflow_kernel(const int*   __restrict__ m,
                         const float* __restrict__ h,
                         const float* __restrict__ u,
                         const float* __restrict__ v,
                         const float* __restrict__ Fxy,
                         const float* __restrict__ Fxu,
                         const float* __restrict__ Fxv,
                         const float* __restrict__ Fyu,
                         const float* __restrict__ Fyv,
                         const float* __restrict__ Fuv,
                         float4*      __restrict__ out) {
    int n = g_cnt[NB * NSEG];
    if (n > CAPN) n = CAPN;
    int total = n * 4;
    for (int i = blockIdx.x * blockDim.x + threadIdx.x; i < total;
         i += gridDim.x * blockDim.x) {
        int k  = i >> 2;
        int q  = i & 3;
        int pt = g_ovf_pt[k];
        int mi = m[pt];
        interp_point(h[2 * pt], h[2 * pt + 1], u[pt], v[pt], mi, pt, q,
                     Fxy, Fxu, Fxv, Fyu, Fyv, Fuv, out);
    }
}

// Fallback if N exceeds static scratch capacity: direct, unsorted, exact.
__global__ void __launch_bounds__(256)
triplane_direct_kernel(const int*   __restrict__ m,
                       const float* __restrict__ h,
                       const float* __restrict__ u,
                       const float* __restrict__ v,
                       const float* __restrict__ Fxy,
                       const float* __restrict__ Fxu,
                       const float* __restrict__ Fxv,
                       const float* __restrict__ Fyu,
                       const float* __restrict__ Fyv,
                       const float* __restrict__ Fuv,
                       float4*      __restrict__ out,
                       int N) {
    int gid = blockIdx.x * blockDim.x + threadIdx.x;
    int pt  = gid >> 2;
    int q   = gid & 3;
    if (pt >= N) return;
    int mi = m[pt];
    interp_point(h[2 * pt], h[2 * pt + 1], u[pt], v[pt], mi, pt, q,
                 Fxy, Fxu, Fxv, Fyu, Fyv, Fuv, out);
}

extern "C" void kernel_launch(void* const* d_in, const int* in_sizes, int n_in,
                              void* d_out, int out_size) {
    // order: r, m, h, u, v, Fxy, Fxu, Fxv, Fyu, Fyv, Fuv   (r unused)
    const int*   m   = (const int*)  d_in[1];
    const float* h   = (const float*)d_in[2];
    const float* u   = (const float*)d_in[3];
    const float* v   = (const float*)d_in[4];
    const float* Fxy = (const float*)d_in[5];
    const float* Fxu = (const float*)d_in[6];
    const float* Fxv = (const float*)d_in[7];
    const float* Fyu = (const float*)d_in[8];
    const float* Fyv = (const float*)d_in[9];
    const float* Fuv = (const float*)d_in[10];

    int N = in_sizes[1];
    int tpb = 256;

    if (N <= CAPN) {
        void* cnt_addr = nullptr;
        cudaGetSymbolAddress(&cnt_addr, g_cnt);
        cudaMemsetAsync(cnt_addr, 0, (NB * NSEG + 1) * sizeof(int));

        scatter_kernel<<<(N + tpb - 1) / tpb, tpb>>>(m, h, u, v, N);
        triplane_bucket_kernel<<<NB * BLOCKS_PER_BUCKET, TPB_MAIN>>>(
            Fxy, Fxu, Fxv, Fyu, Fyv, Fuv, (float4*)d_out);
        triplane_overflow_kernel<<<64, tpb>>>(
            m, h, u, v, Fxy, Fxu, Fxv, Fyu, Fyv, Fuv, (float4*)d_out);
    } else {
        long long tt = (long long)N * 4;
        triplane_direct_kernel<<<(int)((tt + tpb - 1) / tpb), tpb>>>(
            m, h, u, v, Fxy, Fxu, Fxv, Fyu, Fyv, Fuv, (float4*)d_out, N);
    }
}

// round 16
// speedup vs baseline: 1.0887x; 1.0424x over previous
#include <cuda_runtime.h>

#define NHX 64
#define NHY 64
#define NU  512
#define NV  512
#define LCH 16
#define NPLANES 6

#define CAPN 1000000
#define TILE_SHIFT 4                 // 16x16 uv cells per tile
#define TPD 32                       // tiles per dim (512 >> 4)
#define NB (8 * TPD * TPD)           // 8192 buckets
#define CAP 192                      // slots per bucket (mean ~122 at N=1M)

// g_cnt[0..NB-1] = per-bucket counts; g_cnt[NB] = overflow cursor.
// Zeroed each launch by one cudaMemsetAsync node.
__device__ int   g_cnt[NB + 1];
__device__ uint4 g_rec[NB * CAP];    // packed record, 16 B/point
__device__ int   g_ovf_pt[CAPN];     // overflow point ids

#define FR_SCALE 65535.0f
#define FR_INV   (1.0f / 65535.0f)

// ---------------- bucketing / packing ----------------

__device__ __forceinline__ int bucket_of(int mi, float uu, float vv) {
    int uc = (int)(uu * (float)NU); if (uc > NU - 1) uc = NU - 1;
    int vc = (int)(vv * (float)NV); if (vc > NV - 1) vc = NV - 1;
    return (mi << 10) | ((uc >> TILE_SHIFT) << 5) | (vc >> TILE_SHIFT);
}

// exact axis split (same semantics as reference)
__device__ __forceinline__ void axis_split(float ind, int I, int& i1, unsigned& f16) {
    if (ind == (float)I) ind = (float)(I - 1);
    i1 = (int)ind;
    float fr = ind - (float)i1;
    f16 = (unsigned)(fr * FR_SCALE + 0.5f);   // [0, 65535]
}

__global__ void __launch_bounds__(256)
scatter_kernel(const int* __restrict__ m,
               const float* __restrict__ h,
               const float* __restrict__ u,
               const float* __restrict__ v, int N) {
    int pt = blockIdx.x * blockDim.x + threadIdx.x;
    if (pt >= N) return;
    int   mi = m[pt];
    float uu = u[pt], vv = v[pt];
    float2 hh = *reinterpret_cast<const float2*>(h + 2 * pt);

    int b = bucket_of(mi, uu, vv);
    int pos = atomicAdd(&g_cnt[b], 1);
    if (pos < CAP) {
        float ind_hx = (hh.x + 1.0f) / 2.0f * (float)NHX;
        float ind_hy = (hh.y + 1.0f) / 2.0f * (float)NHY;
        float ind_u  = uu * (float)NU;
        float ind_v  = vv * (float)NV;
        int x1, y1, u1, v1; unsigned fx, fy, fu, fv;
        axis_split(ind_hx, NHX, x1, fx);
        axis_split(ind_hy, NHY, y1, fy);
        axis_split(ind_u,  NU,  u1, fu);
        axis_split(ind_v,  NV,  v1, fv);

        uint4 rec;
        rec.x = (fx << 16) | fy;
        rec.y = (fu << 16) | fv;
        rec.z = (unsigned)x1 | ((unsigned)y1 << 6) | ((unsigned)u1 << 12) | ((unsigned)v1 << 21);
        rec.w = (unsigned)pt;
        __stcs(&g_rec[b * CAP + pos], rec);
    } else {
        int o = atomicAdd(&g_cnt[NB], 1);
        if (o < CAPN) g_ovf_pt[o] = pt;
    }
}

// ---------------- interpolation core ----------------

__device__ __forceinline__ float4 bilerp4(const float* __restrict__ F,
                                          int mi, int I, int J,
                                          int i1, int i2, float ir,
                                          int j1, int j2, float jr, int q) {
    int rowA = (mi * I + i1) * J;
    int rowB = (mi * I + i2) * J;
    const float4* p11 = reinterpret_cast<const float4*>(F) + (rowA + j1) * 4 + q;
    const float4* p21 = reinterpret_cast<const float4*>(F) + (rowB + j1) * 4 + q;
    const float4* p12 = reinterpret_cast<const float4*>(F) + (rowA + j2) * 4 + q;
    const float4* p22 = reinterpret_cast<const float4*>(F) + (rowB + j2) * 4 + q;
    float4 a = __ldg(p11);
    float4 b = __ldg(p21);
    float4 c = __ldg(p12);
    float4 d = __ldg(p22);
    float omi = 1.0f - ir, omj = 1.0f - jr;
    float4 out;
    out.x = (a.x * omi + b.x * ir) * omj + (c.x * omi + d.x * ir) * jr;
    out.y = (a.y * omi + b.y * ir) * omj + (c.y * omi + d.y * ir) * jr;
    out.z = (a.z * omi + b.z * ir) * omj + (c.z * omi + d.z * ir) * jr;
    out.w = (a.w * omi + b.w * ir) * omj + (c.w * omi + d.w * ir) * jr;
    return out;
}

// exact axis (overflow + fallback paths)
__device__ __forceinline__ void axis(float ind, int I, int& i1, int& i2, float& fr) {
    if (ind == (float)I) ind = (float)(I - 1);
    i1 = (int)ind;
    fr = ind - (float)i1;
    i2 = i1 + 1;
    if (i2 == I) i2 = 0;
}

__device__ __forceinline__ void interp_core(int mi, int pt, int q,
                                            int x1, int x2, float xr,
                                            int y1, int y2, float yr,
                                            int u1, int u2, float ur,
                                            int v1, int v2, float vr,
                                            const float* __restrict__ Fxy,
                                            const float* __restrict__ Fxu,
                                            const float* __restrict__ Fxv,
                                            const float* __restrict__ Fyu,
                                            const float* __restrict__ Fyv,
                                            const float* __restrict__ Fuv,
                                            float4* __restrict__ out) {
    float4* o = out + (size_t)pt * (NPLANES * (LCH / 4));
    __stcs(&o[0 * 4 + q], bilerp4(Fxy, mi, NHX, NHY, x1, x2, xr, y1, y2, yr, q));
    __stcs(&o[1 * 4 + q], bilerp4(Fxu, mi, NHX, NU,  x1, x2, xr, u1, u2, ur, q));
    __stcs(&o[2 * 4 + q], bilerp4(Fxv, mi, NHX, NV,  x1, x2, xr, v1, v2, vr, q));
    __stcs(&o[3 * 4 + q], bilerp4(Fyu, mi, NHY, NU,  y1, y2, yr, u1, u2, ur, q));
    __stcs(&o[4 * 4 + q], bilerp4(Fyv, mi, NHY, NV,  y1, y2, yr, v1, v2, vr, q));
    __stcs(&o[5 * 4 + q], bilerp4(Fuv, mi, NU,  NV,  u1, u2, ur, v1, v2, vr, q));
}

__device__ __forceinline__ void interp_point(float hx, float hy, float uu, float vv,
                                             int mi, int pt, int q,
                                             const float* __restrict__ Fxy,
                                             const float* __restrict__ Fxu,
                                             const float* __restrict__ Fxv,
                                             const float* __restrict__ Fyu,
                                             const float* __restrict__ Fyv,
                                             const float* __restrict__ Fuv,
                                             float4* __restrict__ out) {
    float ind_hx = (hx + 1.0f) / 2.0f * (float)NHX;
    float ind_hy = (hy + 1.0f) / 2.0f * (float)NHY;
    float ind_u  = uu * (float)NU;
    float ind_v  = vv * (float)NV;
    int x1, x2, y1, y2, u1, u2, v1, v2;
    float xr, yr, ur, vr;
    axis(ind_hx, NHX, x1, x2, xr);
    axis(ind_hy, NHY, y1, y2, yr);
    axis(ind_u,  NU,  u1, u2, ur);
    axis(ind_v,  NV,  v1, v2, vr);
    interp_core(mi, pt, q, x1, x2, xr, y1, y2, yr, u1, u2, ur, v1, v2, vr,
                Fxy, Fxu, Fxv, Fyu, Fyv, Fuv, out);
}

// ---------------- main kernels ----------------

#define TPB_MAIN 256
#define SLOTS_PER_BLOCK (TPB_MAIN / 4)                 // 64
#define BLOCKS_PER_BUCKET (CAP / SLOTS_PER_BLOCK)      // 3

__global__ void __launch_bounds__(TPB_MAIN)
triplane_bucket_kernel(const float* __restrict__ Fxy,
                       const float* __restrict__ Fxu,
                       const float* __restrict__ Fxv,
                       const float* __restrict__ Fyu,
                       const float* __restrict__ Fyv,
                       const float* __restrict__ Fuv,
                       float4*      __restrict__ out) {
    int bucket = blockIdx.x / BLOCKS_PER_BUCKET;
    int sbase  = (blockIdx.x % BLOCKS_PER_BUCKET) * SLOTS_PER_BLOCK;
    int t    = threadIdx.x;
    int slot = sbase + (t >> 2);
    int q    = t & 3;

    int cnt = g_cnt[bucket];
    if (cnt > CAP) cnt = CAP;
    if (slot >= cnt) return;

    uint4 rec = __ldcs(&g_rec[bucket * CAP + slot]);
    int pt = (int)rec.w;
    int mi = bucket >> 10;

    float xr = (float)(rec.x >> 16)     * FR_INV;
    float yr = (float)(rec.x & 0xFFFF)  * FR_INV;
    float ur = (float)(rec.y >> 16)     * FR_INV;
    float vr = (float)(rec.y & 0xFFFF)  * FR_INV;

    int x1 =  rec.z        & 63;
    int y1 = (rec.z >> 6)  & 63;
    int u1 = (rec.z >> 12) & 511;
    int v1 = (rec.z >> 21) & 511;

    int x2 = (x1 + 1) & (NHX - 1);
    int y2 = (y1 + 1) & (NHY - 1);
    int u2 = (u1 + 1) & (NU - 1);
    int v2 = (v1 + 1) & (NV - 1);

    interp_core(mi, pt, q, x1, x2, xr, y1, y2, yr, u1, u2, ur, v1, v2, vr,
                Fxy, Fxu, Fxv, Fyu, Fyv, Fuv, out);
}

// Processes overflow points (normally zero). Grid-stride over g_cnt[NB] * 4 lanes.
__global__ void __launch_bounds__(256)
triplane_overflow_kernel(const int*   __restrict__ m,
                         const float* __restrict__ h,
                         const float* __restrict__ u,
                         const float* __restrict__ v,
                         const float* __restrict__ Fxy,
                         const float* __restrict__ Fxu,
                         const float* __restrict__ Fxv,
                         const float* __restrict__ Fyu,
                         const float* __restrict__ Fyv,
                         const float* __restrict__ Fuv,
                         float4*      __restrict__ out) {
    int n = g_cnt[NB];
    if (n > CAPN) n = CAPN;
    int total = n * 4;
    for (int i = blockIdx.x * blockDim.x + threadIdx.x; i < total;
         i += gridDim.x * blockDim.x) {
        int k  = i >> 2;
        int q  = i & 3;
        int pt = g_ovf_pt[k];
        int mi = m[pt];
        interp_point(h[2 * pt], h[2 * pt + 1], u[pt], v[pt], mi, pt, q,
                     Fxy, Fxu, Fxv, Fyu, Fyv, Fuv, out);
    }
}

// Fallback if N exceeds static scratch capacity: direct, unsorted, exact.
__global__ void __launch_bounds__(256)
triplane_direct_kernel(const int*   __restrict__ m,
                       const float* __restrict__ h,
                       const float* __restrict__ u,
                       const float* __restrict__ v,
                       const float* __restrict__ Fxy,
                       const float* __restrict__ Fxu,
                       const float* __restrict__ Fxv,
                       const float* __restrict__ Fyu,
                       const float* __restrict__ Fyv,
                       const float* __restrict__ Fuv,
                       float4*      __restrict__ out,
                       int N) {
    int gid = blockIdx.x * blockDim.x + threadIdx.x;
    int pt  = gid >> 2;
    int q   = gid & 3;
    if (pt >= N) return;
    int mi = m[pt];
    interp_point(h[2 * pt], h[2 * pt + 1], u[pt], v[pt], mi, pt, q,
                 Fxy, Fxu, Fxv, Fyu, Fyv, Fuv, out);
}

extern "C" void kernel_launch(void* const* d_in, const int* in_sizes, int n_in,
                              void* d_out, int out_size) {
    // order: r, m, h, u, v, Fxy, Fxu, Fxv, Fyu, Fyv, Fuv   (r unused)
    const int*   m   = (const int*)  d_in[1];
    const float* h   = (const float*)d_in[2];
    const float* u   = (const float*)d_in[3];
    const float* v   = (const float*)d_in[4];
    const float* Fxy = (const float*)d_in[5];
    const float* Fxu = (const float*)d_in[6];
    const float* Fxv = (const float*)d_in[7];
    const float* Fyu = (const float*)d_in[8];
    const float* Fyv = (const float*)d_in[9];
    const float* Fuv = (const float*)d_in[10];

    int N = in_sizes[1];
    int tpb = 256;

    if (N <= CAPN) {
        // zero counts + overflow cursor with a single memset node (graph-capturable)
        void* cnt_addr = nullptr;
        cudaGetSymbolAddress(&cnt_addr, g_cnt);
        cudaMemsetAsync(cnt_addr, 0, (NB + 1) * sizeof(int));

        scatter_kernel<<<(N + tpb - 1) / tpb, tpb>>>(m, h, u, v, N);
        triplane_bucket_kernel<<<NB * BLOCKS_PER_BUCKET, TPB_MAIN>>>(
            Fxy, Fxu, Fxv, Fyu, Fyv, Fuv, (float4*)d_out);
        triplane_overflow_kernel<<<64, tpb>>>(
            m, h, u, v, Fxy, Fxu, Fxv, Fyu, Fyv, Fuv, (float4*)d_out);
    } else {
        long long tt = (long long)N * 4;
        triplane_direct_kernel<<<(int)((tt + tpb - 1) / tpb), tpb>>>(
            m, h, u, v, Fxy, Fxu, Fxv, Fyu, Fyv, Fuv, (float4*)d_out, N);
    }
}